// round 2
// baseline (speedup 1.0000x reference)
#include <cuda_runtime.h>
#include <cuda_bf16.h>
#include <math_constants.h>

#define DIM   2048
#define BATCH 32
#define KTOP  256

// Scratch for Bsum[b][i] = sum_j |s[b,i] - s[b,j]|  (32*2048 floats = 256 KB)
__device__ float g_bsum[BATCH * DIM];

// ---------------------------------------------------------------------------
// Kernel 1: all-pairs absolute-difference row sums.
// Grid (32, 8), 256 threads. Each block loads the full 2048-row into smem,
// each thread owns one i and sweeps all j via float4 smem loads.
// 4 independent accumulators break the FADD latency chain.
// ---------------------------------------------------------------------------
__global__ __launch_bounds__(256) void bsum_kernel(const float* __restrict__ scores) {
    __shared__ float s[DIM];
    const int b = blockIdx.x;
    const float* row = scores + b * DIM;

    // cooperative smem fill (vectorized)
    {
        const float4* r4 = (const float4*)row;
        float4* s4 = (float4*)s;
        #pragma unroll
        for (int c = 0; c < DIM / 4 / 256; c++)
            s4[threadIdx.x + c * 256] = r4[threadIdx.x + c * 256];
    }
    __syncthreads();

    const int i = blockIdx.y * 256 + threadIdx.x;
    const float x = s[i];

    const float4* s4 = (const float4*)s;
    float a0 = 0.f, a1 = 0.f, a2 = 0.f, a3 = 0.f;
    #pragma unroll 8
    for (int j = 0; j < DIM / 4; j++) {
        float4 v = s4[j];
        a0 += fabsf(x - v.x);
        a1 += fabsf(x - v.y);
        a2 += fabsf(x - v.z);
        a3 += fabsf(x - v.w);
    }
    g_bsum[b * DIM + i] = (a0 + a1) + (a2 + a3);
}

// ---------------------------------------------------------------------------
// Kernel 2: fused logit + softmax + write.
// One block per (b, k) pair: 8192 blocks, 256 threads, 8 elements/thread in
// registers. logit[i] = s[b,i]*scal(k) - Bsum[b,i]; softmax over i; TAU = 1.
// ---------------------------------------------------------------------------
__global__ __launch_bounds__(256) void softmax_kernel(const float* __restrict__ scores,
                                                      float* __restrict__ out) {
    const int bk = blockIdx.x;           // b*256 + k
    const int b  = bk >> 8;
    const int k  = bk & 255;
    const float scal = (float)(DIM - 1 - 2 * k);   // 2047 - 2k

    const int t = threadIdx.x;
    const float4* sc = (const float4*)(scores + (b << 11));
    const float4* bs = (const float4*)(g_bsum + (b << 11));

    float4 s0 = sc[t];
    float4 s1 = sc[t + 256];
    float4 c0 = bs[t];
    float4 c1 = bs[t + 256];

    float l[8];
    l[0] = fmaf(s0.x, scal, -c0.x);
    l[1] = fmaf(s0.y, scal, -c0.y);
    l[2] = fmaf(s0.z, scal, -c0.z);
    l[3] = fmaf(s0.w, scal, -c0.w);
    l[4] = fmaf(s1.x, scal, -c1.x);
    l[5] = fmaf(s1.y, scal, -c1.y);
    l[6] = fmaf(s1.z, scal, -c1.z);
    l[7] = fmaf(s1.w, scal, -c1.w);

    // --- block max reduction ---
    float m = l[0];
    #pragma unroll
    for (int i = 1; i < 8; i++) m = fmaxf(m, l[i]);
    #pragma unroll
    for (int o = 16; o; o >>= 1) m = fmaxf(m, __shfl_xor_sync(0xffffffffu, m, o));

    __shared__ float red[8];
    const int wid = t >> 5, lane = t & 31;
    if (lane == 0) red[wid] = m;
    __syncthreads();
    float M = red[0];
    #pragma unroll
    for (int w = 1; w < 8; w++) M = fmaxf(M, red[w]);

    // --- exp + block sum reduction ---
    float sum = 0.f;
    #pragma unroll
    for (int i = 0; i < 8; i++) {
        l[i] = __expf(l[i] - M);
        sum += l[i];
    }
    #pragma unroll
    for (int o = 16; o; o >>= 1) sum += __shfl_xor_sync(0xffffffffu, sum, o);

    __syncthreads();                     // red[] reuse
    if (lane == 0) red[wid] = sum;
    __syncthreads();
    float S = 0.f;
    #pragma unroll
    for (int w = 0; w < 8; w++) S += red[w];

    const float inv = __fdividef(1.0f, S);

    float4 o0, o1;
    o0.x = l[0] * inv; o0.y = l[1] * inv; o0.z = l[2] * inv; o0.w = l[3] * inv;
    o1.x = l[4] * inv; o1.y = l[5] * inv; o1.z = l[6] * inv; o1.w = l[7] * inv;

    float4* out4 = (float4*)(out + (size_t)bk * DIM);
    out4[t]       = o0;
    out4[t + 256] = o1;
}

extern "C" void kernel_launch(void* const* d_in, const int* in_sizes, int n_in,
                              void* d_out, int out_size) {
    const float* scores = (const float*)d_in[0];
    float* out = (float*)d_out;

    bsum_kernel<<<dim3(BATCH, DIM / 256), 256>>>(scores);
    softmax_kernel<<<BATCH * KTOP, 256>>>(scores, out);
}

// round 3
// speedup vs baseline: 1.1577x; 1.1577x over previous
#include <cuda_runtime.h>
#include <cuda_bf16.h>
#include <math_constants.h>

#define DIM   2048
#define BATCH 32
#define KTOP  256
#define KPB   8     // k values per softmax block

// Scratch for Bsum[b][i] = sum_j |s[b,i] - s[b,j]|  (32*2048 floats = 256 KB)
__device__ float g_bsum[BATCH * DIM];

__device__ __forceinline__ unsigned long long f32x2_add(unsigned long long a,
                                                        unsigned long long b) {
    unsigned long long r;
    asm("add.rn.f32x2 %0, %1, %2;" : "=l"(r) : "l"(a), "l"(b));
    return r;
}

// ---------------------------------------------------------------------------
// Kernel 1: all-pairs |diff| row sums, packed f32x2.
// Grid (32 b, 32 chunks) x 64 threads: one thread per i, 1024 blocks total
// (6.9 blocks/SM -> ~1% wave quantization). Each block stages the full row in
// smem; every j-iteration is 4 packed fp32 adds (fma pipe) + 4 LOP3 (alu pipe)
// + 1 LDS.128, saturating fma+alu pipes together.
// ---------------------------------------------------------------------------
__global__ __launch_bounds__(64) void bsum_kernel(const float* __restrict__ scores) {
    __shared__ float s[DIM];
    const int b = blockIdx.x;
    const float* row = scores + b * DIM;

    {   // cooperative smem fill: 64 threads x 8 float4
        const float4* r4 = (const float4*)row;
        float4* s4 = (float4*)s;
        #pragma unroll
        for (int c = 0; c < DIM / 4 / 64; c++)
            s4[threadIdx.x + c * 64] = r4[threadIdx.x + c * 64];
    }
    __syncthreads();

    const int i = blockIdx.y * 64 + threadIdx.x;
    const float x = s[i];

    unsigned long long nx;
    {
        unsigned int u = __float_as_uint(-x);
        nx = ((unsigned long long)u << 32) | u;   // (-x, -x)
    }
    const unsigned long long ABSM = 0x7FFFFFFF7FFFFFFFULL;

    const ulonglong2* s2 = (const ulonglong2*)s;
    unsigned long long acc0 = 0ULL, acc1 = 0ULL;  // packed (0.f, 0.f)

    #pragma unroll 8
    for (int j = 0; j < DIM / 4; j++) {
        ulonglong2 v = s2[j];
        unsigned long long d0 = f32x2_add(v.x, nx) & ABSM;  // |v - x| packed
        unsigned long long d1 = f32x2_add(v.y, nx) & ABSM;
        acc0 = f32x2_add(acc0, d0);
        acc1 = f32x2_add(acc1, d1);
    }

    float r = (__uint_as_float((unsigned int)acc0) +
               __uint_as_float((unsigned int)(acc0 >> 32))) +
              (__uint_as_float((unsigned int)acc1) +
               __uint_as_float((unsigned int)(acc1 >> 32)));
    g_bsum[b * DIM + i] = r;
}

// ---------------------------------------------------------------------------
// Kernel 2: fused logit + softmax + write, k-batched.
// Grid (32 kgroups, 32 b) x 256 threads. Each block keeps s[8], c[8] resident
// in registers and produces KPB=8 softmax rows, cutting the redundant
// scores/bsum re-reads 8x. 2 barriers per k via split max/sum smem arrays.
// ---------------------------------------------------------------------------
__global__ __launch_bounds__(256) void softmax_kernel(const float* __restrict__ scores,
                                                      float* __restrict__ out) {
    const int kg = blockIdx.x;           // k group: k = kg*KPB + kk
    const int b  = blockIdx.y;
    const int t  = threadIdx.x;
    const int wid = t >> 5, lane = t & 31;

    const float4* sc = (const float4*)(scores + (b << 11));
    const float4* bs = (const float4*)(g_bsum + (b << 11));

    const float4 s0 = sc[t];
    const float4 s1 = sc[t + 256];
    const float4 c0 = bs[t];
    const float4 c1 = bs[t + 256];

    __shared__ float redM[8];
    __shared__ float redS[8];

    #pragma unroll
    for (int kk = 0; kk < KPB; kk++) {
        const int k = kg * KPB + kk;
        const float scal = (float)(DIM - 1 - 2 * k);   // 2047 - 2k

        float l[8];
        l[0] = fmaf(s0.x, scal, -c0.x);
        l[1] = fmaf(s0.y, scal, -c0.y);
        l[2] = fmaf(s0.z, scal, -c0.z);
        l[3] = fmaf(s0.w, scal, -c0.w);
        l[4] = fmaf(s1.x, scal, -c1.x);
        l[5] = fmaf(s1.y, scal, -c1.y);
        l[6] = fmaf(s1.z, scal, -c1.z);
        l[7] = fmaf(s1.w, scal, -c1.w);

        // block max
        float m = l[0];
        #pragma unroll
        for (int i = 1; i < 8; i++) m = fmaxf(m, l[i]);
        #pragma unroll
        for (int o = 16; o; o >>= 1) m = fmaxf(m, __shfl_xor_sync(0xffffffffu, m, o));
        if (lane == 0) redM[wid] = m;
        __syncthreads();                 // barrier 1
        float M = redM[0];
        #pragma unroll
        for (int w = 1; w < 8; w++) M = fmaxf(M, redM[w]);

        // exp + block sum
        float sum = 0.f;
        #pragma unroll
        for (int i = 0; i < 8; i++) {
            l[i] = __expf(l[i] - M);
            sum += l[i];
        }
        #pragma unroll
        for (int o = 16; o; o >>= 1) sum += __shfl_xor_sync(0xffffffffu, sum, o);
        if (lane == 0) redS[wid] = sum;
        __syncthreads();                 // barrier 2 (also protects redM reuse)
        float S = 0.f;
        #pragma unroll
        for (int w = 0; w < 8; w++) S += redS[w];

        const float inv = __fdividef(1.0f, S);

        float4 o0, o1;
        o0.x = l[0] * inv; o0.y = l[1] * inv; o0.z = l[2] * inv; o0.w = l[3] * inv;
        o1.x = l[4] * inv; o1.y = l[5] * inv; o1.z = l[6] * inv; o1.w = l[7] * inv;

        float4* out4 = (float4*)(out + ((size_t)((b << 8) + k) << 11));
        out4[t]       = o0;
        out4[t + 256] = o1;
    }
}

extern "C" void kernel_launch(void* const* d_in, const int* in_sizes, int n_in,
                              void* d_out, int out_size) {
    const float* scores = (const float*)d_in[0];
    float* out = (float*)d_out;

    bsum_kernel<<<dim3(BATCH, DIM / 64), 64>>>(scores);
    softmax_kernel<<<dim3(KTOP / KPB, BATCH), 256>>>(scores, out);
}